// round 4
// baseline (speedup 1.0000x reference)
#include <cuda_runtime.h>
#include <math.h>

#define D_EMB 1024
#define D_INT 2048
#define N_EXP 8
#define T_TOK 8192
#define ROW_TILES_MAX 264            // ceil((2T + 8*63)/64)
#define PAIR_CAP (ROW_TILES_MAX * 64)

// ---------------- scratch (static device globals; no allocation) -------------
__device__ float g_inter_shared[(size_t)T_TOK * D_INT];     // 64 MB
__device__ float g_inter_routed[(size_t)PAIR_CAP * D_INT];  // ~132 MB
__device__ int   g_pair_token[PAIR_CAP];
__device__ float g_pair_weight[PAIR_CAP];
__device__ int   g_counts[N_EXP];
__device__ int   g_cursor[N_EXP];
__device__ int   g_aligned_off[N_EXP + 1];
__device__ float g_Psum[N_EXP];
__device__ int   g_sel[T_TOK * 2];
__device__ float g_wts[T_TOK * 2];

// ---------------- init: reset per-launch state (graph replays!) --------------
__global__ void k_init() {
    int i = blockIdx.x * blockDim.x + threadIdx.x;
    if (i < PAIR_CAP) { g_pair_token[i] = -1; g_pair_weight[i] = 0.f; }
    if (i < N_EXP)    { g_counts[i] = 0; g_cursor[i] = 0; g_Psum[i] = 0.f; }
}

// ---------------- router: one warp per token ---------------------------------
__global__ void k_router(const float* __restrict__ x, const float* __restrict__ gw) {
    __shared__ float sP[N_EXP];
    __shared__ int   sC[N_EXP];
    const int tid = threadIdx.x;
    if (tid < N_EXP) { sP[tid] = 0.f; sC[tid] = 0; }
    __syncthreads();

    const int warp = tid >> 5, lane = tid & 31;
    const int t = blockIdx.x * 8 + warp;
    const float* xr = x + (size_t)t * D_EMB;

    float acc[N_EXP];
#pragma unroll
    for (int e = 0; e < N_EXP; e++) acc[e] = 0.f;

    for (int d = lane; d < D_EMB; d += 32) {
        float xv = xr[d];
#pragma unroll
        for (int e = 0; e < N_EXP; e++) acc[e] += xv * gw[e * D_EMB + d];
    }
#pragma unroll
    for (int e = 0; e < N_EXP; e++)
#pragma unroll
        for (int o = 16; o > 0; o >>= 1) acc[e] += __shfl_xor_sync(0xffffffffu, acc[e], o);

    if (lane == 0) {
        // top-2 (first-occurrence tie-break, matches lax.top_k)
        int e0 = 0; float v0 = acc[0];
#pragma unroll
        for (int e = 1; e < N_EXP; e++) if (acc[e] > v0) { v0 = acc[e]; e0 = e; }
        int e1 = -1; float v1 = -INFINITY;
#pragma unroll
        for (int e = 0; e < N_EXP; e++) if (e != e0 && acc[e] > v1) { v1 = acc[e]; e1 = e; }
        float ee = expf(v1 - v0);                 // v0 >= v1
        float inv = 1.f / (1.f + ee);
        g_sel[2 * t] = e0; g_sel[2 * t + 1] = e1;
        g_wts[2 * t] = inv; g_wts[2 * t + 1] = ee * inv;
        atomicAdd(&sC[e0], 1); atomicAdd(&sC[e1], 1);

        // full softmax for aux-loss P
        float m = acc[0];
#pragma unroll
        for (int e = 1; e < N_EXP; e++) m = fmaxf(m, acc[e]);
        float p[N_EXP], s = 0.f;
#pragma unroll
        for (int e = 0; e < N_EXP; e++) { p[e] = expf(acc[e] - m); s += p[e]; }
        float is = 1.f / s;
#pragma unroll
        for (int e = 0; e < N_EXP; e++) atomicAdd(&sP[e], p[e] * is);
    }
    __syncthreads();
    if (tid < N_EXP) { atomicAdd(&g_Psum[tid], sP[tid]); atomicAdd(&g_counts[tid], sC[tid]); }
}

// ---------------- offsets (64-aligned segments) + aux loss -------------------
__global__ void k_offsets_aux(float* __restrict__ out, int aux_idx) {
    if (threadIdx.x == 0 && blockIdx.x == 0) {
        int off = 0; float aux = 0.f;
        for (int e = 0; e < N_EXP; e++) {
            g_aligned_off[e] = off;
            off += (g_counts[e] + 63) & ~63;
            aux += ((float)g_counts[e] / (float)(T_TOK * 2)) * (g_Psum[e] / (float)T_TOK);
        }
        g_aligned_off[N_EXP] = off;
        out[aux_idx] = aux * (float)N_EXP;
    }
}

// ---------------- scatter: warp-aggregated cursor ----------------------------
__global__ void k_scatter() {
    const int t = blockIdx.x * blockDim.x + threadIdx.x;
    const int lane = threadIdx.x & 31;
#pragma unroll
    for (int k = 0; k < 2; k++) {
        int e = g_sel[2 * t + k];
        float w = g_wts[2 * t + k];
        unsigned mask = __match_any_sync(0xffffffffu, e);
        int leader = __ffs(mask) - 1;
        int rank = __popc(mask & ((1u << lane) - 1u));
        int base = 0;
        if (lane == leader) base = atomicAdd(&g_cursor[e], __popc(mask));
        base = __shfl_sync(0xffffffffu, base, leader);
        int pos = g_aligned_off[e] + base + rank;
        g_pair_token[pos] = t;
        g_pair_weight[pos] = w;
    }
}

// ---------------- fused gate/up GEMM + SiLU*up -------------------------------
// 64x64 tile, BK=16, 256 threads, 4x4 per-thread tile, dual accumulators.
template <bool ROUTED>
__global__ __launch_bounds__(256)
void k_gateup(const float* __restrict__ X,
              const float* __restrict__ Wg_all,
              const float* __restrict__ Wu_all) {
    __shared__ float Xs[16][65];
    __shared__ float Gs[16][64];
    __shared__ float Us[16][64];
    __shared__ int   toks[64];

    const int tid = threadIdx.x;
    const int n0 = blockIdx.x * 64;
    const int m0 = blockIdx.y * 64;

    const float* Wg;
    const float* Wu;
    if (ROUTED) {
        if (m0 >= g_aligned_off[N_EXP]) return;
        int e = 0;
#pragma unroll
        for (int i = 1; i < N_EXP; i++) if (m0 >= g_aligned_off[i]) e = i;
        Wg = Wg_all + (size_t)e * D_EMB * D_INT;
        Wu = Wu_all + (size_t)e * D_EMB * D_INT;
        if (tid < 64) toks[tid] = g_pair_token[m0 + tid];
    } else {
        Wg = Wg_all; Wu = Wu_all;
        if (tid < 64) toks[tid] = m0 + tid;
    }
    __syncthreads();

    const int lrow = tid >> 2;
    const int lk4  = (tid & 3) * 4;
    const int wk   = tid >> 4;
    const int wc4  = (tid & 15) * 4;
    const int tx = tid & 15, ty = tid >> 4;

    const int trow = toks[lrow];
    const float* xrow = X + (size_t)(trow >= 0 ? trow : 0) * D_EMB;

    float accg[4][4], accu[4][4];
#pragma unroll
    for (int i = 0; i < 4; i++)
#pragma unroll
        for (int j = 0; j < 4; j++) { accg[i][j] = 0.f; accu[i][j] = 0.f; }

    for (int k0 = 0; k0 < D_EMB; k0 += 16) {
        float4 xv = make_float4(0.f, 0.f, 0.f, 0.f);
        if (trow >= 0) xv = *(const float4*)(xrow + k0 + lk4);
        Xs[lk4 + 0][lrow] = xv.x; Xs[lk4 + 1][lrow] = xv.y;
        Xs[lk4 + 2][lrow] = xv.z; Xs[lk4 + 3][lrow] = xv.w;
        *(float4*)&Gs[wk][wc4] = *(const float4*)(Wg + (size_t)(k0 + wk) * D_INT + n0 + wc4);
        *(float4*)&Us[wk][wc4] = *(const float4*)(Wu + (size_t)(k0 + wk) * D_INT + n0 + wc4);
        __syncthreads();
#pragma unroll
        for (int k = 0; k < 16; k++) {
            float a[4], bg[4], bu[4];
#pragma unroll
            for (int i = 0; i < 4; i++) a[i] = Xs[k][ty * 4 + i];
#pragma unroll
            for (int j = 0; j < 4; j++) { bg[j] = Gs[k][tx * 4 + j]; bu[j] = Us[k][tx * 4 + j]; }
#pragma unroll
            for (int i = 0; i < 4; i++)
#pragma unroll
                for (int j = 0; j < 4; j++) {
                    accg[i][j] += a[i] * bg[j];
                    accu[i][j] += a[i] * bu[j];
                }
        }
        __syncthreads();
    }

    float* inter = ROUTED ? g_inter_routed : g_inter_shared;
#pragma unroll
    for (int i = 0; i < 4; i++) {
        float4 r;
        float* pr = &r.x;
#pragma unroll
        for (int j = 0; j < 4; j++) {
            float g = accg[i][j];
            float s = g / (1.f + __expf(-g));   // SiLU
            pr[j] = s * accu[i][j];
        }
        *(float4*)(inter + (size_t)(m0 + ty * 4 + i) * D_INT + n0 + tx * 4) = r;
    }
}

// ---------------- down GEMM (+ weighted scatter for routed) ------------------
template <bool ROUTED>
__global__ __launch_bounds__(256)
void k_down(const float* __restrict__ Wd_all, float* __restrict__ out) {
    __shared__ float Is[16][65];
    __shared__ float Ws[16][64];
    __shared__ int   toks[64];
    __shared__ float wts[64];

    const int tid = threadIdx.x;
    const int n0 = blockIdx.x * 64;
    const int m0 = blockIdx.y * 64;

    const float* Wd;
    if (ROUTED) {
        if (m0 >= g_aligned_off[N_EXP]) return;
        int e = 0;
#pragma unroll
        for (int i = 1; i < N_EXP; i++) if (m0 >= g_aligned_off[i]) e = i;
        Wd = Wd_all + (size_t)e * D_INT * D_EMB;
        if (tid < 64) { toks[tid] = g_pair_token[m0 + tid]; wts[tid] = g_pair_weight[m0 + tid]; }
    } else {
        Wd = Wd_all;
    }
    __syncthreads();

    const float* inter = ROUTED ? g_inter_routed : g_inter_shared;

    const int lrow = tid >> 2;
    const int lk4  = (tid & 3) * 4;
    const int wk   = tid >> 4;
    const int wc4  = (tid & 15) * 4;
    const int tx = tid & 15, ty = tid >> 4;

    float acc[4][4];
#pragma unroll
    for (int i = 0; i < 4; i++)
#pragma unroll
        for (int j = 0; j < 4; j++) acc[i][j] = 0.f;

    for (int k0 = 0; k0 < D_INT; k0 += 16) {
        float4 iv = *(const float4*)(inter + (size_t)(m0 + lrow) * D_INT + k0 + lk4);
        Is[lk4 + 0][lrow] = iv.x; Is[lk4 + 1][lrow] = iv.y;
        Is[lk4 + 2][lrow] = iv.z; Is[lk4 + 3][lrow] = iv.w;
        *(float4*)&Ws[wk][wc4] = *(const float4*)(Wd + (size_t)(k0 + wk) * D_EMB + n0 + wc4);
        __syncthreads();
#pragma unroll
        for (int k = 0; k < 16; k++) {
            float a[4], b[4];
#pragma unroll
            for (int i = 0; i < 4; i++) a[i] = Is[k][ty * 4 + i];
#pragma unroll
            for (int j = 0; j < 4; j++) b[j] = Ws[k][tx * 4 + j];
#pragma unroll
            for (int i = 0; i < 4; i++)
#pragma unroll
                for (int j = 0; j < 4; j++) acc[i][j] += a[i] * b[j];
        }
        __syncthreads();
    }

    if (ROUTED) {
#pragma unroll
        for (int i = 0; i < 4; i++) {
            int r = ty * 4 + i;
            int t = toks[r];
            if (t < 0) continue;
            float w = wts[r];
#pragma unroll
            for (int j = 0; j < 4; j++)
                atomicAdd(&out[(size_t)t * D_EMB + n0 + tx * 4 + j], w * acc[i][j]);
        }
    } else {
#pragma unroll
        for (int i = 0; i < 4; i++) {
            float4 r4;
            float* pr = &r4.x;
#pragma unroll
            for (int j = 0; j < 4; j++) pr[j] = acc[i][j];
            *(float4*)(out + (size_t)(m0 + ty * 4 + i) * D_EMB + n0 + tx * 4) = r4;
        }
    }
}

// ---------------- launch ------------------------------------------------------
extern "C" void kernel_launch(void* const* d_in, const int* in_sizes, int n_in,
                              void* d_out, int out_size) {
    const float* x  = (const float*)d_in[0];   // hidden_states [4,2048,1024]
    const float* gw = (const float*)d_in[1];   // gate_w        [8,1024]
    const float* sg = (const float*)d_in[2];   // shared_gate   [1024,2048]
    const float* su = (const float*)d_in[3];   // shared_up     [1024,2048]
    const float* sd = (const float*)d_in[4];   // shared_down   [2048,1024]
    const float* eg = (const float*)d_in[5];   // exp_gate      [8,1024,2048]
    const float* eu = (const float*)d_in[6];   // exp_up        [8,1024,2048]
    const float* ed = (const float*)d_in[7];   // exp_down      [8,2048,1024]
    float* out = (float*)d_out;

    k_init<<<(PAIR_CAP + 255) / 256, 256>>>();
    k_router<<<T_TOK / 8, 256>>>(x, gw);
    k_offsets_aux<<<1, 32>>>(out, out_size - 1);
    k_scatter<<<T_TOK / 256, 256>>>();

    k_gateup<false><<<dim3(D_INT / 64, T_TOK / 64), 256>>>(x, sg, su);
    k_down<false><<<dim3(D_EMB / 64, T_TOK / 64), 256>>>(sd, out);

    k_gateup<true><<<dim3(D_INT / 64, ROW_TILES_MAX), 256>>>(x, eg, eu);
    k_down<true><<<dim3(D_EMB / 64, ROW_TILES_MAX), 256>>>(ed, out);
}

// round 5
// speedup vs baseline: 1.0011x; 1.0011x over previous
#include <cuda_runtime.h>
#include <math.h>

#define D_EMB 1024
#define D_INT 2048
#define N_EXP 8
#define T_TOK 8192
#define ROW_TILES_MAX 264            // ceil((2T + 8*63)/64)
#define PAIR_CAP (ROW_TILES_MAX * 64)

// ---------------- scratch (static device globals; no allocation) -------------
__device__ float g_inter_shared[(size_t)T_TOK * D_INT];     // 64 MB
__device__ float g_inter_routed[(size_t)PAIR_CAP * D_INT];  // ~132 MB
__device__ int   g_pair_token[PAIR_CAP];
__device__ float g_pair_weight[PAIR_CAP];
__device__ int   g_counts[N_EXP];
__device__ int   g_cursor[N_EXP];
__device__ int   g_aligned_off[N_EXP + 1];
__device__ float g_Psum[N_EXP];
__device__ int   g_sel[T_TOK * 2];
__device__ float g_wts[T_TOK * 2];

// ---------------- init: reset per-launch state (graph replays!) --------------
__global__ void k_init() {
    int i = blockIdx.x * blockDim.x + threadIdx.x;
    if (i < PAIR_CAP) { g_pair_token[i] = -1; g_pair_weight[i] = 0.f; }
    if (i < N_EXP)    { g_counts[i] = 0; g_cursor[i] = 0; g_Psum[i] = 0.f; }
}

// ---------------- router: one warp per token ---------------------------------
__global__ void k_router(const float* __restrict__ x, const float* __restrict__ gw) {
    __shared__ float sP[N_EXP];
    __shared__ int   sC[N_EXP];
    const int tid = threadIdx.x;
    if (tid < N_EXP) { sP[tid] = 0.f; sC[tid] = 0; }
    __syncthreads();

    const int warp = tid >> 5, lane = tid & 31;
    const int t = blockIdx.x * 8 + warp;
    const float* xr = x + (size_t)t * D_EMB;

    float acc[N_EXP];
#pragma unroll
    for (int e = 0; e < N_EXP; e++) acc[e] = 0.f;

    for (int d = lane; d < D_EMB; d += 32) {
        float xv = xr[d];
#pragma unroll
        for (int e = 0; e < N_EXP; e++) acc[e] += xv * gw[e * D_EMB + d];
    }
#pragma unroll
    for (int e = 0; e < N_EXP; e++)
#pragma unroll
        for (int o = 16; o > 0; o >>= 1) acc[e] += __shfl_xor_sync(0xffffffffu, acc[e], o);

    if (lane == 0) {
        // top-2 (first-occurrence tie-break, matches lax.top_k)
        int e0 = 0; float v0 = acc[0];
#pragma unroll
        for (int e = 1; e < N_EXP; e++) if (acc[e] > v0) { v0 = acc[e]; e0 = e; }
        int e1 = -1; float v1 = -INFINITY;
#pragma unroll
        for (int e = 0; e < N_EXP; e++) if (e != e0 && acc[e] > v1) { v1 = acc[e]; e1 = e; }
        float ee = expf(v1 - v0);                 // v0 >= v1
        float inv = 1.f / (1.f + ee);
        g_sel[2 * t] = e0; g_sel[2 * t + 1] = e1;
        g_wts[2 * t] = inv; g_wts[2 * t + 1] = ee * inv;
        atomicAdd(&sC[e0], 1); atomicAdd(&sC[e1], 1);

        // full softmax for aux-loss P
        float m = acc[0];
#pragma unroll
        for (int e = 1; e < N_EXP; e++) m = fmaxf(m, acc[e]);
        float p[N_EXP], s = 0.f;
#pragma unroll
        for (int e = 0; e < N_EXP; e++) { p[e] = expf(acc[e] - m); s += p[e]; }
        float is = 1.f / s;
#pragma unroll
        for (int e = 0; e < N_EXP; e++) atomicAdd(&sP[e], p[e] * is);
    }
    __syncthreads();
    if (tid < N_EXP) { atomicAdd(&g_Psum[tid], sP[tid]); atomicAdd(&g_counts[tid], sC[tid]); }
}

// ---------------- offsets (64-aligned segments) + aux loss -------------------
__global__ void k_offsets_aux(float* __restrict__ out, int aux_idx) {
    if (threadIdx.x == 0 && blockIdx.x == 0) {
        int off = 0; float aux = 0.f;
        for (int e = 0; e < N_EXP; e++) {
            g_aligned_off[e] = off;
            off += (g_counts[e] + 63) & ~63;
            aux += ((float)g_counts[e] / (float)(T_TOK * 2)) * (g_Psum[e] / (float)T_TOK);
        }
        g_aligned_off[N_EXP] = off;
        out[aux_idx] = aux * (float)N_EXP;
    }
}

// ---------------- scatter: warp-aggregated cursor ----------------------------
__global__ void k_scatter() {
    const int t = blockIdx.x * blockDim.x + threadIdx.x;
    const int lane = threadIdx.x & 31;
#pragma unroll
    for (int k = 0; k < 2; k++) {
        int e = g_sel[2 * t + k];
        float w = g_wts[2 * t + k];
        unsigned mask = __match_any_sync(0xffffffffu, e);
        int leader = __ffs(mask) - 1;
        int rank = __popc(mask & ((1u << lane) - 1u));
        int base = 0;
        if (lane == leader) base = atomicAdd(&g_cursor[e], __popc(mask));
        base = __shfl_sync(0xffffffffu, base, leader);
        int pos = g_aligned_off[e] + base + rank;
        g_pair_token[pos] = t;
        g_pair_weight[pos] = w;
    }
}

// ---------------- fused gate/up GEMM + SiLU*up -------------------------------
// 64x64 tile, BK=16, 256 threads, 4x4 per-thread tile, dual accumulators.
template <bool ROUTED>
__global__ __launch_bounds__(256)
void k_gateup(const float* __restrict__ X,
              const float* __restrict__ Wg_all,
              const float* __restrict__ Wu_all) {
    __shared__ float Xs[16][65];
    __shared__ float Gs[16][64];
    __shared__ float Us[16][64];
    __shared__ int   toks[64];

    const int tid = threadIdx.x;
    const int n0 = blockIdx.x * 64;
    const int m0 = blockIdx.y * 64;

    const float* Wg;
    const float* Wu;
    if (ROUTED) {
        if (m0 >= g_aligned_off[N_EXP]) return;
        int e = 0;
#pragma unroll
        for (int i = 1; i < N_EXP; i++) if (m0 >= g_aligned_off[i]) e = i;
        Wg = Wg_all + (size_t)e * D_EMB * D_INT;
        Wu = Wu_all + (size_t)e * D_EMB * D_INT;
        if (tid < 64) toks[tid] = g_pair_token[m0 + tid];
    } else {
        Wg = Wg_all; Wu = Wu_all;
        if (tid < 64) toks[tid] = m0 + tid;
    }
    __syncthreads();

    const int lrow = tid >> 2;
    const int lk4  = (tid & 3) * 4;
    const int wk   = tid >> 4;
    const int wc4  = (tid & 15) * 4;
    const int tx = tid & 15, ty = tid >> 4;

    const int trow = toks[lrow];
    const float* xrow = X + (size_t)(trow >= 0 ? trow : 0) * D_EMB;

    float accg[4][4], accu[4][4];
#pragma unroll
    for (int i = 0; i < 4; i++)
#pragma unroll
        for (int j = 0; j < 4; j++) { accg[i][j] = 0.f; accu[i][j] = 0.f; }

    for (int k0 = 0; k0 < D_EMB; k0 += 16) {
        float4 xv = make_float4(0.f, 0.f, 0.f, 0.f);
        if (trow >= 0) xv = *(const float4*)(xrow + k0 + lk4);
        Xs[lk4 + 0][lrow] = xv.x; Xs[lk4 + 1][lrow] = xv.y;
        Xs[lk4 + 2][lrow] = xv.z; Xs[lk4 + 3][lrow] = xv.w;
        *(float4*)&Gs[wk][wc4] = *(const float4*)(Wg + (size_t)(k0 + wk) * D_INT + n0 + wc4);
        *(float4*)&Us[wk][wc4] = *(const float4*)(Wu + (size_t)(k0 + wk) * D_INT + n0 + wc4);
        __syncthreads();
#pragma unroll
        for (int k = 0; k < 16; k++) {
            float a[4], bg[4], bu[4];
#pragma unroll
            for (int i = 0; i < 4; i++) a[i] = Xs[k][ty * 4 + i];
#pragma unroll
            for (int j = 0; j < 4; j++) { bg[j] = Gs[k][tx * 4 + j]; bu[j] = Us[k][tx * 4 + j]; }
#pragma unroll
            for (int i = 0; i < 4; i++)
#pragma unroll
                for (int j = 0; j < 4; j++) {
                    accg[i][j] += a[i] * bg[j];
                    accu[i][j] += a[i] * bu[j];
                }
        }
        __syncthreads();
    }

    float* inter = ROUTED ? g_inter_routed : g_inter_shared;
#pragma unroll
    for (int i = 0; i < 4; i++) {
        float4 r;
        float* pr = &r.x;
#pragma unroll
        for (int j = 0; j < 4; j++) {
            float g = accg[i][j];
            float s = g / (1.f + __expf(-g));   // SiLU
            pr[j] = s * accu[i][j];
        }
        *(float4*)(inter + (size_t)(m0 + ty * 4 + i) * D_INT + n0 + tx * 4) = r;
    }
}

// ---------------- down GEMM (+ weighted scatter for routed) ------------------
template <bool ROUTED>
__global__ __launch_bounds__(256)
void k_down(const float* __restrict__ Wd_all, float* __restrict__ out) {
    __shared__ float Is[16][65];
    __shared__ float Ws[16][64];
    __shared__ int   toks[64];
    __shared__ float wts[64];

    const int tid = threadIdx.x;
    const int n0 = blockIdx.x * 64;
    const int m0 = blockIdx.y * 64;

    const float* Wd;
    if (ROUTED) {
        if (m0 >= g_aligned_off[N_EXP]) return;
        int e = 0;
#pragma unroll
        for (int i = 1; i < N_EXP; i++) if (m0 >= g_aligned_off[i]) e = i;
        Wd = Wd_all + (size_t)e * D_INT * D_EMB;
        if (tid < 64) { toks[tid] = g_pair_token[m0 + tid]; wts[tid] = g_pair_weight[m0 + tid]; }
    } else {
        Wd = Wd_all;
    }
    __syncthreads();

    const float* inter = ROUTED ? g_inter_routed : g_inter_shared;

    const int lrow = tid >> 2;
    const int lk4  = (tid & 3) * 4;
    const int wk   = tid >> 4;
    const int wc4  = (tid & 15) * 4;
    const int tx = tid & 15, ty = tid >> 4;

    float acc[4][4];
#pragma unroll
    for (int i = 0; i < 4; i++)
#pragma unroll
        for (int j = 0; j < 4; j++) acc[i][j] = 0.f;

    for (int k0 = 0; k0 < D_INT; k0 += 16) {
        float4 iv = *(const float4*)(inter + (size_t)(m0 + lrow) * D_INT + k0 + lk4);
        Is[lk4 + 0][lrow] = iv.x; Is[lk4 + 1][lrow] = iv.y;
        Is[lk4 + 2][lrow] = iv.z; Is[lk4 + 3][lrow] = iv.w;
        *(float4*)&Ws[wk][wc4] = *(const float4*)(Wd + (size_t)(k0 + wk) * D_EMB + n0 + wc4);
        __syncthreads();
#pragma unroll
        for (int k = 0; k < 16; k++) {
            float a[4], b[4];
#pragma unroll
            for (int i = 0; i < 4; i++) a[i] = Is[k][ty * 4 + i];
#pragma unroll
            for (int j = 0; j < 4; j++) b[j] = Ws[k][tx * 4 + j];
#pragma unroll
            for (int i = 0; i < 4; i++)
#pragma unroll
                for (int j = 0; j < 4; j++) acc[i][j] += a[i] * b[j];
        }
        __syncthreads();
    }

    if (ROUTED) {
#pragma unroll
        for (int i = 0; i < 4; i++) {
            int r = ty * 4 + i;
            int t = toks[r];
            if (t < 0) continue;
            float w = wts[r];
#pragma unroll
            for (int j = 0; j < 4; j++)
                atomicAdd(&out[(size_t)t * D_EMB + n0 + tx * 4 + j], w * acc[i][j]);
        }
    } else {
#pragma unroll
        for (int i = 0; i < 4; i++) {
            float4 r4;
            float* pr = &r4.x;
#pragma unroll
            for (int j = 0; j < 4; j++) pr[j] = acc[i][j];
            *(float4*)(out + (size_t)(m0 + ty * 4 + i) * D_EMB + n0 + tx * 4) = r4;
        }
    }
}

// ---------------- launch ------------------------------------------------------
extern "C" void kernel_launch(void* const* d_in, const int* in_sizes, int n_in,
                              void* d_out, int out_size) {
    const float* x  = (const float*)d_in[0];   // hidden_states [4,2048,1024]
    const float* gw = (const float*)d_in[1];   // gate_w        [8,1024]
    const float* sg = (const float*)d_in[2];   // shared_gate   [1024,2048]
    const float* su = (const float*)d_in[3];   // shared_up     [1024,2048]
    const float* sd = (const float*)d_in[4];   // shared_down   [2048,1024]
    const float* eg = (const float*)d_in[5];   // exp_gate      [8,1024,2048]
    const float* eu = (const float*)d_in[6];   // exp_up        [8,1024,2048]
    const float* ed = (const float*)d_in[7];   // exp_down      [8,2048,1024]
    float* out = (float*)d_out;

    k_init<<<(PAIR_CAP + 255) / 256, 256>>>();
    k_router<<<T_TOK / 8, 256>>>(x, gw);
    k_offsets_aux<<<1, 32>>>(out, out_size - 1);
    k_scatter<<<T_TOK / 256, 256>>>();

    k_gateup<false><<<dim3(D_INT / 64, T_TOK / 64), 256>>>(x, sg, su);
    k_down<false><<<dim3(D_EMB / 64, T_TOK / 64), 256>>>(sd, out);

    k_gateup<true><<<dim3(D_INT / 64, ROW_TILES_MAX), 256>>>(x, eg, eu);
    k_down<true><<<dim3(D_EMB / 64, ROW_TILES_MAX), 256>>>(ed, out);
}